// round 10
// baseline (speedup 1.0000x reference)
#include <cuda_runtime.h>

// ---------------------------------------------------------------------------
// VQEmbedding: int8 dp4a candidate pass (integer-exact Q) + exact fp32 rescore.
// N=131072 pixels, D=64, K=1024 codes.
// Final selection bit-matches reference:
//   G = seq fp32 FMA over d ; dist = rn( rn(S+T) - 2G ) ; argmin, low-idx ties
// Output layout (float32): [ out : 8388608 | loss : 1 | indices : 131072 ]
// ---------------------------------------------------------------------------

#define NUM_K 1024
#define D 64
#define TN 128
#define OUT_ELEMS 8388608
#define LOSS_OFF  8388608
#define IDX_OFF   8388609

// smem float offsets
#define AF_F    0        // float Af[128][68]            = 8704
#define WOUT_F  8704     // overlay: wout[64][132]=8448 (valid only post-rescore)
#define AQ_F    8704     // int Aq[16][132]              = 2112
#define WQ_F    10816    // int 2 x [16][68]             = 2176
#define TS_F    12992    // float [1024]
#define DQ_F    14016    // int [128]
#define GMAX_F  14144    // int [128]
#define CAND_F  14272    // int [128][48]                = 6144  (ends 20416)
#define BKS_F   20416    // int [128]
#define RED_F   20544    // float [8]
#define SS_F    20552    // float [128]
#define SMEM_FLOATS 20680                               // ~82.7 KB

__device__ __align__(16) int   g_wqT[16 * NUM_K];  // packed qw, [g][k]
__device__ __align__(16) float g_T[NUM_K];         // exact sum(w^2)
__device__ int g_mxw_i = 0, g_L1w_i = 0, g_Tmax_i = 0;
__device__ double g_loss_sum;

__device__ __forceinline__ unsigned s2u(const void* p) {
    unsigned a;
    asm("{ .reg .u64 t; cvta.to.shared.u64 t, %1; cvt.u32.u64 %0, t; }"
        : "=r"(a) : "l"(p));
    return a;
}

// ---------------------------------------------------------------------------
// Prep1: per-code exact T_k (seq), L1, max|w|; global maxima. Zero loss.
// ---------------------------------------------------------------------------
__global__ __launch_bounds__(256)
void vq_prep1(const float* __restrict__ w) {
    int k = blockIdx.x * 256 + threadIdx.x;     // 1024 threads
    if (k == 0) g_loss_sum = 0.0;
    if (k < NUM_K) {
        const float* r = w + k * D;
        float T = 0.f, L1 = 0.f, mx = 0.f;
        #pragma unroll
        for (int d = 0; d < D; d++) {
            float v = r[d];
            T = __fadd_rn(T, __fmul_rn(v, v));
            L1 += fabsf(v);
            mx = fmaxf(mx, fabsf(v));
        }
        g_T[k] = T;
        atomicMax(&g_Tmax_i, __float_as_int(T));
        atomicMax(&g_L1w_i, __float_as_int(L1));
        atomicMax(&g_mxw_i, __float_as_int(mx));
    }
}

// Prep2: quantize w to int8 with global scale, pack transposed [g][k].
__global__ __launch_bounds__(256)
void vq_prep2(const float* __restrict__ w) {
    int k = blockIdx.x * 256 + threadIdx.x;
    if (k >= NUM_K) return;
    float mxw = __int_as_float(g_mxw_i);
    float rw = (mxw > 1e-30f) ? 127.f / mxw : 0.f;
    const float4* r = (const float4*)(w + k * D);
    #pragma unroll
    for (int g = 0; g < 16; g++) {
        float4 v = r[g];
        int q0 = __float2int_rn(v.x * rw);
        int q1 = __float2int_rn(v.y * rw);
        int q2 = __float2int_rn(v.z * rw);
        int q3 = __float2int_rn(v.w * rw);
        g_wqT[g * NUM_K + k] = (q0 & 255) | ((q1 & 255) << 8) |
                               ((q2 & 255) << 16) | ((q3 & 255) << 24);
    }
}

// stage one 16(g) x 64(k) packed-W chunk into buffer buf
__device__ __forceinline__ void stage_chunk(float* smf, int buf, int c, int tid) {
    int* dst = (int*)(smf + WQ_F) + buf * (16 * 68);
    const int* src = g_wqT + c * 64;
    if (tid < 256) {
        int g = tid >> 4, cc = (tid & 15) << 2;      // 256 16B chunks
        unsigned sa = s2u(dst + g * 68 + cc);
        asm volatile("cp.async.cg.shared.global [%0], [%1], 16;"
                     :: "r"(sa), "l"(src + g * NUM_K + cc));
    }
    asm volatile("cp.async.commit_group;" ::: "memory");
}

__device__ __forceinline__ float exact_dist(const float* xr, const float* wp,
                                            float Sp, float Tk) {
    const float4* wr = (const float4*)wp;
    float G = 0.f;
    #pragma unroll
    for (int q = 0; q < 16; q++) {
        float4 wv = wr[q];
        G = __fmaf_rn(xr[q * 4 + 0], wv.x, G);
        G = __fmaf_rn(xr[q * 4 + 1], wv.y, G);
        G = __fmaf_rn(xr[q * 4 + 2], wv.z, G);
        G = __fmaf_rn(xr[q * 4 + 3], wv.w, G);
    }
    return __fmaf_rn(-2.f, G, __fadd_rn(Sp, Tk));
}

// ---------------------------------------------------------------------------
extern __shared__ float smf[];

__global__ __launch_bounds__(256, 2)
void vq_main(const float* __restrict__ x, const float* __restrict__ w,
             float* __restrict__ out) {
    float* Af    = smf + AF_F;              // [n][68]
    int*   aqs   = (int*)(smf + AQ_F);      // [g][132]
    float* tsp   = smf + TS_F;
    int*   dqs   = (int*)(smf + DQ_F);
    int*   gmaxs = (int*)(smf + GMAX_F);
    int*   cands = (int*)(smf + CAND_F);    // [128][48]
    int*   bks   = (int*)(smf + BKS_F);
    float* red   = smf + RED_F;
    float* Ss    = smf + SS_F;

    const int tid = threadIdx.x;
    const int tx = tid & 15;                // k: 4 codes per chunk
    const int ty = tid >> 4;                // n: 8 pixels
    const int n0 = blockIdx.x * TN;
    const int b  = n0 >> 12;
    const int hw0 = n0 & 4095;
    const float* xb = x + ((size_t)b << 18);

    stage_chunk(smf, 0, 0, tid);
    {   // T table
        unsigned sa = s2u(tsp + tid * 4);
        asm volatile("cp.async.cg.shared.global [%0], [%1], 16;"
                     :: "r"(sa), "l"(g_T + tid * 4));
        asm volatile("cp.async.commit_group;" ::: "memory");
    }
    for (int e = tid; e < TN * D; e += 256) {
        int d = e >> 7, n = e & 127;
        Af[n * 68 + d] = xb[(d << 12) + hw0 + n];
    }
    asm volatile("cp.async.wait_group 0;" ::: "memory");
    __syncthreads();

    // per-pixel setup: exact S (seq), L1, max; int8 quantize; integer band dq
    if (tid < TN) {
        const float* r = Af + tid * 68;
        float S = 0.f, L1 = 0.f, mx = 0.f;
        #pragma unroll
        for (int d = 0; d < D; d++) {
            float v = r[d];
            S = __fadd_rn(S, __fmul_rn(v, v));
            L1 += fabsf(v);
            mx = fmaxf(mx, fabsf(v));
        }
        Ss[tid] = S;
        float aw   = __int_as_float(g_mxw_i) * (1.f / 127.f);
        float L1w  = __int_as_float(g_L1w_i);
        float Tmax = __int_as_float(g_Tmax_i);
        float ax = mx * (1.f / 127.f);
        float rq = (mx > 1e-20f) ? 127.f / mx : 0.f;
        const float4* rv = (const float4*)r;
        #pragma unroll
        for (int g = 0; g < 16; g++) {
            float4 v = rv[g];
            int q0 = __float2int_rn(v.x * rq);
            int q1 = __float2int_rn(v.y * rq);
            int q2 = __float2int_rn(v.z * rq);
            int q3 = __float2int_rn(v.w * rq);
            aqs[g * 132 + tid] = (q0 & 255) | ((q1 & 255) << 8) |
                                 ((q2 & 255) << 16) | ((q3 & 255) << 24);
        }
        float eps = (2.f * (0.5f * aw * L1 + 0.5f * ax * L1w + 16.f * ax * aw)
                     + Tmax + 1e-5f) * 1.25f;
        float fdq = fminf(eps / (ax * aw), 1.0e9f);   // inf/nan -> 1e9
        dqs[tid] = (int)fdq + 2;
        gmaxs[tid] = -(1 << 30);
    }
    __syncthreads();

    int dqv[8], lmax[8], cnt8[8];
    #pragma unroll
    for (int n = 0; n < 8; n++) {
        dqv[n] = dqs[(ty << 3) + n];
        lmax[n] = -(1 << 30);
        cnt8[n] = 0;
    }

    // ---- int8 dp4a GEMM over 16 chunks of 64 codes ----
    #pragma unroll 1
    for (int c = 0; c < 16; c++) {
        const int* Wq = (int*)(smf + WQ_F) + (c & 1) * (16 * 68);
        if (c < 15) stage_chunk(smf, (c + 1) & 1, c + 1, tid);

        int acc[32];
        #pragma unroll
        for (int i = 0; i < 32; i++) acc[i] = 0;

        #pragma unroll
        for (int g = 0; g < 16; g++) {
            int4 a0 = *(const int4*)(aqs + g * 132 + (ty << 3));
            int4 a1 = *(const int4*)(aqs + g * 132 + (ty << 3) + 4);
            int4 wv = *(const int4*)(Wq + g * 68 + (tx << 2));
            int av[8] = {a0.x, a0.y, a0.z, a0.w, a1.x, a1.y, a1.z, a1.w};
            #pragma unroll
            for (int n = 0; n < 8; n++) {
                acc[n * 4 + 0] = __dp4a(av[n], wv.x, acc[n * 4 + 0]);
                acc[n * 4 + 1] = __dp4a(av[n], wv.y, acc[n * 4 + 1]);
                acc[n * 4 + 2] = __dp4a(av[n], wv.z, acc[n * 4 + 2]);
                acc[n * 4 + 3] = __dp4a(av[n], wv.w, acc[n * 4 + 3]);
            }
        }

        // integer candidate capture (superset of true argmin, proven band)
        const int kb = (c << 6) + (tx << 2);
        #pragma unroll
        for (int n = 0; n < 8; n++) {
            int m4 = max(max(acc[n * 4], acc[n * 4 + 1]),
                         max(acc[n * 4 + 2], acc[n * 4 + 3]));
            if (m4 > lmax[n]) lmax[n] = m4;
            int rn = (ty << 3) + n;
            int gm = gmaxs[rn];
            int mr = gm > lmax[n] ? gm : lmax[n];
            int thr = mr - dqv[n];
            if (m4 >= thr) {
                #pragma unroll
                for (int j = 0; j < 4; j++) {
                    if (acc[n * 4 + j] >= thr) {
                        if (cnt8[n] < 3)
                            cands[rn * 48 + tx * 3 + cnt8[n]] = kb + j;
                        cnt8[n]++;
                    }
                }
                if (m4 > gm) atomicMax(&gmaxs[rn], m4);
            }
        }

        if (c < 15) asm volatile("cp.async.wait_group 0;" ::: "memory");
        __syncthreads();
    }

    // ---- exact fp32 rescore: per-thread over its candidates (or own slice) ----
    #pragma unroll 1
    for (int n = 0; n < 8; n++) {
        int rn = (ty << 3) + n;
        float Sp = Ss[rn];
        const float* xr = Af + rn * 68;
        float bd = 1e30f; int bk = 0x7fffffff;
        if (cnt8[n] > 3) {
            // own 64-code slice, ascending k (exact, parallel fallback)
            #pragma unroll 1
            for (int c = 0; c < 16; c++) {
                #pragma unroll
                for (int j = 0; j < 4; j++) {
                    int k = (c << 6) + (tx << 2) + j;
                    float dvx = exact_dist(xr, w + (k << 6), Sp, tsp[k]);
                    if (dvx < bd || (dvx == bd && k < bk)) { bd = dvx; bk = k; }
                }
            }
        } else {
            #pragma unroll 1
            for (int s = 0; s < cnt8[n]; s++) {
                int k = cands[rn * 48 + tx * 3 + s];
                float dvx = exact_dist(xr, w + (k << 6), Sp, tsp[k]);
                if (dvx < bd || (dvx == bd && k < bk)) { bd = dvx; bk = k; }
            }
        }
        // reduce across 16 tx lanes (same 16-lane group); low index wins ties
        #pragma unroll
        for (int off = 8; off; off >>= 1) {
            float ov = __shfl_xor_sync(0xffffffffu, bd, off);
            int   oi = __shfl_xor_sync(0xffffffffu, bk, off);
            if (ov < bd || (ov == bd && oi < bk)) { bd = ov; bk = oi; }
        }
        if (tx == 0) bks[rn] = bk;
    }
    __syncthreads();

    // gather chosen codewords into overlay wout[64][132] (coalesced scatter)
    float* wout = smf + WOUT_F;
    if (tid < TN) {
        int k = bks[tid];
        const float4* src = (const float4*)(w + (k << 6));
        #pragma unroll
        for (int j = 0; j < 16; j++) {
            float4 v = src[j];
            int d = j * 4;
            wout[(d + 0) * 132 + tid] = v.x;
            wout[(d + 1) * 132 + tid] = v.y;
            wout[(d + 2) * 132 + tid] = v.z;
            wout[(d + 3) * 132 + tid] = v.w;
        }
    }
    __syncthreads();

    const size_t ob = ((size_t)b << 18);
    float lsum = 0.f;
    for (int e = tid; e < TN * D; e += 256) {
        int d = e >> 7, n = e & 127;
        float wv = wout[d * 132 + n];
        float xv = Af[n * 68 + d];
        out[ob + (d << 12) + hw0 + n] = wv;
        float df = xv - wv;
        lsum += df * df;
    }
    if (tid < TN) out[IDX_OFF + n0 + tid] = (float)bks[tid];

    #pragma unroll
    for (int off = 16; off; off >>= 1)
        lsum += __shfl_xor_sync(0xffffffffu, lsum, off);
    if ((tid & 31) == 0) red[tid >> 5] = lsum;
    __syncthreads();
    if (tid == 0) {
        float s = 0.f;
        #pragma unroll
        for (int i = 0; i < 8; i++) s += red[i];
        atomicAdd(&g_loss_sum, (double)s);
    }
}

__global__ void vq_fin(float* __restrict__ out) {
    if (threadIdx.x == 0)
        out[LOSS_OFF] = (float)(1.25 * g_loss_sum / (double)OUT_ELEMS);
}

// ---------------------------------------------------------------------------
extern "C" void kernel_launch(void* const* d_in, const int* in_sizes, int n_in,
                              void* d_out, int out_size) {
    const float* x = (const float*)d_in[0];   // [32,64,64,64] f32
    const float* w = (const float*)d_in[1];   // [1024,64] f32
    float* out = (float*)d_out;

    const int SMEM_BYTES = SMEM_FLOATS * 4;
    cudaFuncSetAttribute(vq_main, cudaFuncAttributeMaxDynamicSharedMemorySize,
                         SMEM_BYTES);

    vq_prep1<<<4, 256>>>(w);
    vq_prep2<<<4, 256>>>(w);
    vq_main<<<1024, 256, SMEM_BYTES>>>(x, w, out);
    vq_fin<<<1, 32>>>(out);
}

// round 11
// speedup vs baseline: 4.3911x; 4.3911x over previous
#include <cuda_runtime.h>

// ---------------------------------------------------------------------------
// VQEmbedding, exact fp32 FFMA2 GEMM + argmin. Persistent work-stealing CTAs.
//   G_nk = seq fp32 FMA over d ; dist = rn( rn(S+T) - 2G ) ; argmin low-idx
// Output layout (float32): [ out : 8388608 | loss : 1 | indices : 131072 ]
// ---------------------------------------------------------------------------

#define TN 128
#define TK 64
#define APAD 132           // A row stride (floats)
#define WPAD 68            // W chunk row stride (floats)
#define NUM_K 1024
#define D 64
#define WOFF (D * WPAD)    // one W buffer, floats (4352)
#define NTILES 1024
#define NCTAS 296          // 2 CTAs/SM x 148 SMs
#define OUT_ELEMS 8388608
#define LOSS_OFF  8388608
#define IDX_OFF   8388609

// smem float offsets
#define A_F    0                       // [64][132]      = 8448 floats
#define W_F    8448                    // 2 x [64][68]   = 8704
#define TS_F   17152                   // [1024]
#define SS_F   18176                   // [128]
#define BK_F   18304                   // [128] (ints)
#define RED_F  18432                   // [8]
#define SMEM_FLOATS 18440              // ~73.8 KB

__device__ __align__(16) float g_T[NUM_K];        // exact sum(w^2)
__device__ __align__(16) float g_wT[D * NUM_K];   // w transposed [d][k]
__device__ double g_loss_sum;
__device__ unsigned g_tile_ctr;

typedef unsigned long long ull;

__device__ __forceinline__ ull pack2(float x, float y) {
    ull r;
    asm("mov.b64 %0, {%1, %2};" : "=l"(r)
        : "r"(__float_as_uint(x)), "r"(__float_as_uint(y)));
    return r;
}
__device__ __forceinline__ void unpack2(ull p, float &x, float &y) {
    unsigned a, b;
    asm("mov.b64 {%0, %1}, %2;" : "=r"(a), "=r"(b) : "l"(p));
    x = __uint_as_float(a); y = __uint_as_float(b);
}
#define FMA2(d, a, b, c) \
    asm("fma.rn.f32x2 %0, %1, %2, %3;" : "=l"(d) : "l"(a), "l"(b), "l"(c))

// ---------------------------------------------------------------------------
// Prep: 16 blocks transpose w -> g_wT, exact T_k, zero loss + tile counter.
// ---------------------------------------------------------------------------
__global__ __launch_bounds__(256)
void vq_prep(const float* __restrict__ w) {
    __shared__ float s[64][65];
    const int t = threadIdx.x;
    const int kb = blockIdx.x * 64;
    if (blockIdx.x == 0 && t == 0) { g_loss_sum = 0.0; g_tile_ctr = 0u; }
    {
        int k = t >> 2, dq = (t & 3) << 4;
        const float4* src = (const float4*)(w + (kb + k) * D + dq);
        float4 v0 = src[0], v1 = src[1], v2 = src[2], v3 = src[3];
        s[dq+ 0][k]=v0.x; s[dq+ 1][k]=v0.y; s[dq+ 2][k]=v0.z; s[dq+ 3][k]=v0.w;
        s[dq+ 4][k]=v1.x; s[dq+ 5][k]=v1.y; s[dq+ 6][k]=v1.z; s[dq+ 7][k]=v1.w;
        s[dq+ 8][k]=v2.x; s[dq+ 9][k]=v2.y; s[dq+10][k]=v2.z; s[dq+11][k]=v2.w;
        s[dq+12][k]=v3.x; s[dq+13][k]=v3.y; s[dq+14][k]=v3.z; s[dq+15][k]=v3.w;
    }
    __syncthreads();
    {
        int d = t >> 2, kq = (t & 3) << 4;
        float4* dst = (float4*)(g_wT + d * NUM_K + kb + kq);
        #pragma unroll
        for (int j = 0; j < 4; j++) {
            float4 o;
            o.x = s[d][kq + 4*j + 0]; o.y = s[d][kq + 4*j + 1];
            o.z = s[d][kq + 4*j + 2]; o.w = s[d][kq + 4*j + 3];
            dst[j] = o;
        }
    }
    if (t < 64) {
        float acc = 0.f;
        #pragma unroll
        for (int d = 0; d < D; d++) {
            float v = s[d][t];
            acc = __fadd_rn(acc, __fmul_rn(v, v));
        }
        g_T[kb + t] = acc;
    }
}

// ---------------------------------------------------------------------------
__device__ __forceinline__ unsigned s2u(const void* p) {
    unsigned a;
    asm("{ .reg .u64 t; cvta.to.shared.u64 t, %1; cvt.u32.u64 %0, t; }"
        : "=r"(a) : "l"(p));
    return a;
}

// stage one 64(d) x 64(k) W chunk (g_wT cols c*64..) into buffer buf
__device__ __forceinline__ void stage_chunk(float* smf, int buf, int c, int tid) {
    float* dst = smf + W_F + buf * WOFF;
    const float* src = g_wT + c * TK;
    #pragma unroll
    for (int i = 0; i < 4; i++) {
        int idx = tid + i * 256;           // 0..1023 float4 chunks
        int d = idx >> 4, kk = (idx & 15) << 2;
        unsigned sa = s2u(dst + d * WPAD + kk);
        asm volatile("cp.async.cg.shared.global [%0], [%1], 16;"
                     :: "r"(sa), "l"(src + d * NUM_K + kk));
    }
    asm volatile("cp.async.commit_group;" ::: "memory");
}

extern __shared__ float smf[];

__global__ __launch_bounds__(256, 2)
void vq_main(const float* __restrict__ x, const float* __restrict__ w,
             float* __restrict__ out) {
    float* As  = smf + A_F;
    float* tsp = smf + TS_F;
    float* Ss  = smf + SS_F;
    int*   bks = (int*)(smf + BK_F);
    float* red = smf + RED_F;

    const int tid = threadIdx.x;
    const int tx = tid & 15;          // k: 4 codes
    const int ty = tid >> 4;          // n: 8 pixels

    // stage T table once per CTA
    {
        unsigned sa = s2u(tsp + tid * 4);
        asm volatile("cp.async.cg.shared.global [%0], [%1], 16;"
                     :: "r"(sa), "l"(g_T + tid * 4));
        asm volatile("cp.async.commit_group;" ::: "memory");
        asm volatile("cp.async.wait_group 0;" ::: "memory");
    }
    __shared__ unsigned s_tile;

    for (;;) {
        if (tid == 0) s_tile = atomicAdd(&g_tile_ctr, 1u);
        __syncthreads();
        const unsigned tile = s_tile;
        __syncthreads();               // everyone read s_tile before next write
        if (tile >= NTILES) break;

        const int n0 = (int)tile * TN;
        const int b  = n0 >> 12;
        const int hw0 = n0 & 4095;
        const float* xb = x + ((size_t)b << 18);

        stage_chunk(smf, 0, 0, tid);
        for (int e = tid; e < TN * D; e += 256) {
            int nl = e & 127, d = e >> 7;
            As[d * APAD + nl] = xb[(d << 12) + hw0 + nl];
        }
        asm volatile("cp.async.wait_group 0;" ::: "memory");
        __syncthreads();

        if (tid < TN) {                // exact S_n, sequential d
            float s = 0.f;
            #pragma unroll
            for (int d = 0; d < D; d++) {
                float v = As[d * APAD + tid];
                s = __fadd_rn(s, __fmul_rn(v, v));
            }
            Ss[tid] = s;
        }
        __syncthreads();

        float s8[8];
        #pragma unroll
        for (int i = 0; i < 8; i++) s8[i] = Ss[(ty << 3) + i];

        float bestv[8];
        int   besti[8];
        #pragma unroll
        for (int i = 0; i < 8; i++) { bestv[i] = 3.4e38f; besti[i] = 0; }

        #pragma unroll 1
        for (int c = 0; c < 16; c++) {
            const int kc = c << 6;
            const float* cur = smf + W_F + (c & 1) * WOFF;
            if (c < 15) stage_chunk(smf, (c + 1) & 1, c + 1, tid);

            const int kb = kc + (tx << 2);
            float tk0 = tsp[kb],     tk1 = tsp[kb + 1];
            float tk2 = tsp[kb + 2], tk3 = tsp[kb + 3];

            ull acc[16];
            #pragma unroll
            for (int i = 0; i < 16; i++) acc[i] = 0ull;

            const float* Ar0 = As + (ty << 3);
            const float* Wr0 = cur + (tx << 2);
            #pragma unroll 8
            for (int d = 0; d < D; d++) {
                const float* Ar = Ar0 + d * APAD;
                const float* Wr = Wr0 + d * WPAD;
                ulonglong2 a01 = ((const ulonglong2*)Ar)[0];
                ulonglong2 a23 = ((const ulonglong2*)Ar)[1];
                float4 wv = *(const float4*)Wr;
                ull wd0 = pack2(wv.x, wv.x), wd1 = pack2(wv.y, wv.y);
                ull wd2 = pack2(wv.z, wv.z), wd3 = pack2(wv.w, wv.w);
                FMA2(acc[ 0], a01.x, wd0, acc[ 0]);
                FMA2(acc[ 1], a01.y, wd0, acc[ 1]);
                FMA2(acc[ 2], a23.x, wd0, acc[ 2]);
                FMA2(acc[ 3], a23.y, wd0, acc[ 3]);
                FMA2(acc[ 4], a01.x, wd1, acc[ 4]);
                FMA2(acc[ 5], a01.y, wd1, acc[ 5]);
                FMA2(acc[ 6], a23.x, wd1, acc[ 6]);
                FMA2(acc[ 7], a23.y, wd1, acc[ 7]);
                FMA2(acc[ 8], a01.x, wd2, acc[ 8]);
                FMA2(acc[ 9], a01.y, wd2, acc[ 9]);
                FMA2(acc[10], a23.x, wd2, acc[10]);
                FMA2(acc[11], a23.y, wd2, acc[11]);
                FMA2(acc[12], a01.x, wd3, acc[12]);
                FMA2(acc[13], a01.y, wd3, acc[13]);
                FMA2(acc[14], a23.x, wd3, acc[14]);
                FMA2(acc[15], a23.y, wd3, acc[15]);
            }

            float tkv[4] = {tk0, tk1, tk2, tk3};
            #pragma unroll
            for (int k = 0; k < 4; k++) {
                float T = tkv[k];
                int kg = kb + k;
                #pragma unroll
                for (int np = 0; np < 4; np++) {
                    float G0, G1;
                    unpack2(acc[k * 4 + np], G0, G1);
                    float u0 = __fadd_rn(s8[2*np],     T);
                    float u1 = __fadd_rn(s8[2*np + 1], T);
                    float d0 = __fmaf_rn(-2.f, G0, u0);
                    float d1 = __fmaf_rn(-2.f, G1, u1);
                    if (d0 < bestv[2*np]) { bestv[2*np] = d0; besti[2*np] = kg; }
                    if (d1 < bestv[2*np+1]) { bestv[2*np+1] = d1; besti[2*np+1] = kg; }
                }
            }

            if (c < 15) asm volatile("cp.async.wait_group 0;" ::: "memory");
            __syncthreads();
        }

        // reduce over the 16 tx lanes; smaller index wins exact ties
        #pragma unroll
        for (int i = 0; i < 8; i++) {
            float v = bestv[i]; int bi = besti[i];
            #pragma unroll
            for (int off = 8; off; off >>= 1) {
                float ov = __shfl_xor_sync(0xffffffffu, v, off);
                int   oi = __shfl_xor_sync(0xffffffffu, bi, off);
                if (ov < v || (ov == v && oi < bi)) { v = ov; bi = oi; }
            }
            if (tx == 0) bks[(ty << 3) + i] = bi;
        }
        __syncthreads();

        // gather chosen codewords into W region for coalesced NCHW scatter
        float* wout = smf + W_F;       // 8704 floats >= 64*132 overlay
        if (tid < TN) {
            int k = bks[tid];
            const float4* src = (const float4*)(w + (k << 6));
            #pragma unroll
            for (int j = 0; j < 16; j++) {
                float4 v = src[j];
                int d = j * 4;
                wout[(d + 0) * APAD + tid] = v.x;
                wout[(d + 1) * APAD + tid] = v.y;
                wout[(d + 2) * APAD + tid] = v.z;
                wout[(d + 3) * APAD + tid] = v.w;
            }
        }
        __syncthreads();

        const size_t ob = ((size_t)b << 18);
        float lsum = 0.f;
        for (int e = tid; e < TN * D; e += 256) {
            int nl = e & 127, d = e >> 7;
            float wv = wout[d * APAD + nl];
            float xv = As[d * APAD + nl];
            out[ob + (d << 12) + hw0 + nl] = wv;
            float df = xv - wv;
            lsum += df * df;
        }
        if (tid < TN) out[IDX_OFF + n0 + tid] = (float)bks[tid];

        #pragma unroll
        for (int off = 16; off; off >>= 1)
            lsum += __shfl_xor_sync(0xffffffffu, lsum, off);
        if ((tid & 31) == 0) red[tid >> 5] = lsum;
        __syncthreads();
        if (tid == 0) {
            float s = 0.f;
            #pragma unroll
            for (int i = 0; i < 8; i++) s += red[i];
            atomicAdd(&g_loss_sum, (double)s);
        }
        __syncthreads();               // red/wout reuse safe before next tile
    }
}

__global__ void vq_fin(float* __restrict__ out) {
    if (threadIdx.x == 0)
        out[LOSS_OFF] = (float)(1.25 * g_loss_sum / (double)OUT_ELEMS);
}

// ---------------------------------------------------------------------------
extern "C" void kernel_launch(void* const* d_in, const int* in_sizes, int n_in,
                              void* d_out, int out_size) {
    const float* x = (const float*)d_in[0];   // [32,64,64,64] f32
    const float* w = (const float*)d_in[1];   // [1024,64] f32
    float* out = (float*)d_out;

    const int SMEM_BYTES = SMEM_FLOATS * 4;
    cudaFuncSetAttribute(vq_main, cudaFuncAttributeMaxDynamicSharedMemorySize,
                         SMEM_BYTES);

    vq_prep<<<16, 256>>>(w);
    vq_main<<<NCTAS, 256, SMEM_BYTES>>>(x, w, out);
    vq_fin<<<1, 32>>>(out);
}

// round 12
// speedup vs baseline: 4.5986x; 1.0473x over previous
#include <cuda_runtime.h>

// ---------------------------------------------------------------------------
// VQEmbedding, exact fp32 FFMA2 GEMM + argmin. Grid launch, fin folded in.
//   G_nk = seq fp32 FMA over d ; dist = rn( rn(S+T) - 2G ) ; argmin low-idx
// Output layout (float32): [ out : 8388608 | loss : 1 | indices : 131072 ]
// ---------------------------------------------------------------------------

#define TN 128
#define TK 64
#define APAD 132           // A row stride (floats)
#define WPAD 68            // W chunk row stride (floats)
#define NUM_K 1024
#define D 64
#define WOFF (D * WPAD)    // one W buffer, floats (4352)
#define NTILES 1024
#define OUT_ELEMS 8388608
#define LOSS_OFF  8388608
#define IDX_OFF   8388609

// smem float offsets
#define A_F    0                       // [64][132]      = 8448 floats
#define W_F    8448                    // 2 x [64][68]   = 8704
#define TS_F   17152                   // [1024]
#define SS_F   18176                   // [128]
#define BK_F   18304                   // [128] (ints)
#define RED_F  18432                   // [8]
#define SMEM_FLOATS 18440              // ~73.8 KB

__device__ __align__(16) float g_T[NUM_K];        // exact sum(w^2)
__device__ __align__(16) float g_wT[D * NUM_K];   // w transposed [d][k]
__device__ double g_loss_sum;
__device__ unsigned g_done;

typedef unsigned long long ull;

__device__ __forceinline__ ull pack2(float x, float y) {
    ull r;
    asm("mov.b64 %0, {%1, %2};" : "=l"(r)
        : "r"(__float_as_uint(x)), "r"(__float_as_uint(y)));
    return r;
}
__device__ __forceinline__ void unpack2(ull p, float &x, float &y) {
    unsigned a, b;
    asm("mov.b64 {%0, %1}, %2;" : "=r"(a), "=r"(b) : "l"(p));
    x = __uint_as_float(a); y = __uint_as_float(b);
}
#define FMA2(d, a, b, c) \
    asm("fma.rn.f32x2 %0, %1, %2, %3;" : "=l"(d) : "l"(a), "l"(b), "l"(c))

// ---------------------------------------------------------------------------
// Prep: 16 blocks transpose w -> g_wT, exact T_k, zero loss + done counter.
// ---------------------------------------------------------------------------
__global__ __launch_bounds__(256)
void vq_prep(const float* __restrict__ w) {
    __shared__ float s[64][65];
    const int t = threadIdx.x;
    const int kb = blockIdx.x * 64;
    if (blockIdx.x == 0 && t == 0) { g_loss_sum = 0.0; g_done = 0u; }
    {
        int k = t >> 2, dq = (t & 3) << 4;
        const float4* src = (const float4*)(w + (kb + k) * D + dq);
        float4 v0 = src[0], v1 = src[1], v2 = src[2], v3 = src[3];
        s[dq+ 0][k]=v0.x; s[dq+ 1][k]=v0.y; s[dq+ 2][k]=v0.z; s[dq+ 3][k]=v0.w;
        s[dq+ 4][k]=v1.x; s[dq+ 5][k]=v1.y; s[dq+ 6][k]=v1.z; s[dq+ 7][k]=v1.w;
        s[dq+ 8][k]=v2.x; s[dq+ 9][k]=v2.y; s[dq+10][k]=v2.z; s[dq+11][k]=v2.w;
        s[dq+12][k]=v3.x; s[dq+13][k]=v3.y; s[dq+14][k]=v3.z; s[dq+15][k]=v3.w;
    }
    __syncthreads();
    {
        int d = t >> 2, kq = (t & 3) << 4;
        float4* dst = (float4*)(g_wT + d * NUM_K + kb + kq);
        #pragma unroll
        for (int j = 0; j < 4; j++) {
            float4 o;
            o.x = s[d][kq + 4*j + 0]; o.y = s[d][kq + 4*j + 1];
            o.z = s[d][kq + 4*j + 2]; o.w = s[d][kq + 4*j + 3];
            dst[j] = o;
        }
    }
    if (t < 64) {
        float acc = 0.f;
        #pragma unroll
        for (int d = 0; d < D; d++) {
            float v = s[d][t];
            acc = __fadd_rn(acc, __fmul_rn(v, v));
        }
        g_T[kb + t] = acc;
    }
}

// ---------------------------------------------------------------------------
__device__ __forceinline__ unsigned s2u(const void* p) {
    unsigned a;
    asm("{ .reg .u64 t; cvta.to.shared.u64 t, %1; cvt.u32.u64 %0, t; }"
        : "=r"(a) : "l"(p));
    return a;
}

// stage one 64(d) x 64(k) W chunk (g_wT cols c*64..) into buffer buf
__device__ __forceinline__ void stage_chunk(float* smf, int buf, int c, int tid) {
    float* dst = smf + W_F + buf * WOFF;
    const float* src = g_wT + c * TK;
    #pragma unroll
    for (int i = 0; i < 4; i++) {
        int idx = tid + i * 256;           // 0..1023 float4 chunks
        int d = idx >> 4, kk = (idx & 15) << 2;
        unsigned sa = s2u(dst + d * WPAD + kk);
        asm volatile("cp.async.cg.shared.global [%0], [%1], 16;"
                     :: "r"(sa), "l"(src + d * NUM_K + kk));
    }
    asm volatile("cp.async.commit_group;" ::: "memory");
}

extern __shared__ float smf[];

__global__ __launch_bounds__(256, 2)
void vq_main(const float* __restrict__ x, const float* __restrict__ w,
             float* __restrict__ out) {
    float* As  = smf + A_F;
    float* tsp = smf + TS_F;
    float* Ss  = smf + SS_F;
    int*   bks = (int*)(smf + BK_F);
    float* red = smf + RED_F;

    const int tid = threadIdx.x;
    const int tx = tid & 15;          // k: 4 codes
    const int ty = tid >> 4;          // n: 8 pixels
    const int n0 = blockIdx.x * TN;
    const int b  = n0 >> 12;
    const int hw0 = n0 & 4095;
    const float* xb = x + ((size_t)b << 18);

    // stage W chunk 0 + T table
    stage_chunk(smf, 0, 0, tid);
    {
        unsigned sa = s2u(tsp + tid * 4);
        asm volatile("cp.async.cg.shared.global [%0], [%1], 16;"
                     :: "r"(sa), "l"(g_T + tid * 4));
        asm volatile("cp.async.commit_group;" ::: "memory");
    }
    for (int e = tid; e < TN * D; e += 256) {
        int nl = e & 127, d = e >> 7;
        As[d * APAD + nl] = xb[(d << 12) + hw0 + nl];
    }
    asm volatile("cp.async.wait_group 0;" ::: "memory");
    __syncthreads();

    if (tid < TN) {                    // exact S_n, sequential d
        float s = 0.f;
        #pragma unroll
        for (int d = 0; d < D; d++) {
            float v = As[d * APAD + tid];
            s = __fadd_rn(s, __fmul_rn(v, v));
        }
        Ss[tid] = s;
    }
    __syncthreads();

    float s8[8];
    #pragma unroll
    for (int i = 0; i < 8; i++) s8[i] = Ss[(ty << 3) + i];

    float bestv[8];
    int   besti[8];
    #pragma unroll
    for (int i = 0; i < 8; i++) { bestv[i] = 3.4e38f; besti[i] = 0; }

    #pragma unroll 1
    for (int c = 0; c < 16; c++) {
        const int kc = c << 6;
        const float* cur = smf + W_F + (c & 1) * WOFF;
        if (c < 15) stage_chunk(smf, (c + 1) & 1, c + 1, tid);

        const int kb = kc + (tx << 2);
        float tk0 = tsp[kb],     tk1 = tsp[kb + 1];
        float tk2 = tsp[kb + 2], tk3 = tsp[kb + 3];

        ull acc[16];
        #pragma unroll
        for (int i = 0; i < 16; i++) acc[i] = 0ull;

        const float* Ar0 = As + (ty << 3);
        const float* Wr0 = cur + (tx << 2);
        #pragma unroll 8
        for (int d = 0; d < D; d++) {
            const float* Ar = Ar0 + d * APAD;
            const float* Wr = Wr0 + d * WPAD;
            ulonglong2 a01 = ((const ulonglong2*)Ar)[0];   // (n0,n1),(n2,n3)
            ulonglong2 a23 = ((const ulonglong2*)Ar)[1];   // (n4,n5),(n6,n7)
            float4 wv = *(const float4*)Wr;
            ull wd0 = pack2(wv.x, wv.x), wd1 = pack2(wv.y, wv.y);
            ull wd2 = pack2(wv.z, wv.z), wd3 = pack2(wv.w, wv.w);
            FMA2(acc[ 0], a01.x, wd0, acc[ 0]);
            FMA2(acc[ 1], a01.y, wd0, acc[ 1]);
            FMA2(acc[ 2], a23.x, wd0, acc[ 2]);
            FMA2(acc[ 3], a23.y, wd0, acc[ 3]);
            FMA2(acc[ 4], a01.x, wd1, acc[ 4]);
            FMA2(acc[ 5], a01.y, wd1, acc[ 5]);
            FMA2(acc[ 6], a01.x, wd2, acc[ 6]);
            FMA2(acc[ 7], a23.x, wd1, acc[ 7]);
            FMA2(acc[ 8], a23.y, wd1, acc[ 8]);
            FMA2(acc[ 9], a01.y, wd2, acc[ 9]);
            FMA2(acc[10], a23.x, wd2, acc[10]);
            FMA2(acc[11], a23.y, wd2, acc[11]);
            FMA2(acc[12], a01.x, wd3, acc[12]);
            FMA2(acc[13], a01.y, wd3, acc[13]);
            FMA2(acc[14], a23.x, wd3, acc[14]);
            FMA2(acc[15], a23.y, wd3, acc[15]);
        }

        // exact scoring: d = rn( rn(S+T) - 2G ); running argmin (low idx ties)
        // acc index mapping: logical (k,np): 0..5,7,8 reordered above; fix here
        // (k0:acc0-3 np0-3) (k1:acc4,5? careful) -- use explicit map:
        // k0: a01x*wd0=acc0, a01y*wd0=acc1, a23x*wd0=acc2, a23y*wd0=acc3
        // k1: a01x=acc4, a01y=acc7? NO -- see mapping comment below.
        {
            // mapping table generated from the FMA2 order above:
            // acc: 0:(k0,np0) 1:(k0,np1) 2:(k0,np2) 3:(k0,np3)
            //      4:(k1,np0) 5:(k1,np1)? -> acc5 = a01.y*wd1 = (k1,np1)
            //      6:(k2,np0) 7:(k1,np2) 8:(k1,np3) 9:(k2,np1)
            //     10:(k2,np2)11:(k2,np3)12:(k3,np0)13:(k3,np1)
            //     14:(k3,np2)15:(k3,np3)
            const int map_k [16] = {0,0,0,0, 1,1,2,1, 1,2,2,2, 3,3,3,3};
            const int map_np[16] = {0,1,2,3, 0,1,0,2, 3,1,2,3, 0,1,2,3};
            float tkv[4] = {tk0, tk1, tk2, tk3};
            #pragma unroll
            for (int i = 0; i < 16; i++) {
                int k = map_k[i], np = map_np[i];
                float T = tkv[k];
                int kg = kb + k;
                float G0, G1;
                unpack2(acc[i], G0, G1);
                float u0 = __fadd_rn(s8[2*np],     T);
                float u1 = __fadd_rn(s8[2*np + 1], T);
                float d0 = __fmaf_rn(-2.f, G0, u0);
                float d1 = __fmaf_rn(-2.f, G1, u1);
                if (d0 < bestv[2*np]) { bestv[2*np] = d0; besti[2*np] = kg; }
                if (d1 < bestv[2*np+1]) { bestv[2*np+1] = d1; besti[2*np+1] = kg; }
            }
        }

        if (c < 15) asm volatile("cp.async.wait_group 0;" ::: "memory");
        __syncthreads();
    }

    // reduce over the 16 tx lanes; smaller index wins exact ties
    #pragma unroll
    for (int i = 0; i < 8; i++) {
        float v = bestv[i]; int bi = besti[i];
        #pragma unroll
        for (int off = 8; off; off >>= 1) {
            float ov = __shfl_xor_sync(0xffffffffu, v, off);
            int   oi = __shfl_xor_sync(0xffffffffu, bi, off);
            if (ov < v || (ov == v && oi < bi)) { v = ov; bi = oi; }
        }
        if (tx == 0) bks[(ty << 3) + i] = bi;
    }
    __syncthreads();

    // gather chosen codewords: 2 threads per pixel (256 threads, 8 f4 each)
    float* wout = smf + W_F;           // 8704 floats >= 64*132 overlay
    {
        int p = tid >> 1, half = tid & 1;       // pixel, which 32-d half
        int k = bks[p];
        const float4* src = (const float4*)(w + (k << 6)) + half * 8;
        #pragma unroll
        for (int j = 0; j < 8; j++) {
            float4 v = src[j];
            int d = half * 32 + j * 4;
            wout[(d + 0) * APAD + p] = v.x;
            wout[(d + 1) * APAD + p] = v.y;
            wout[(d + 2) * APAD + p] = v.z;
            wout[(d + 3) * APAD + p] = v.w;
        }
    }
    __syncthreads();

    const size_t ob = ((size_t)b << 18);
    float lsum = 0.f;
    for (int e = tid; e < TN * D; e += 256) {
        int nl = e & 127, d = e >> 7;
        float wv = wout[d * APAD + nl];
        float xv = As[d * APAD + nl];
        out[ob + (d << 12) + hw0 + nl] = wv;
        float df = xv - wv;
        lsum += df * df;
    }
    if (tid < TN) out[IDX_OFF + n0 + tid] = (float)bks[tid];

    #pragma unroll
    for (int off = 16; off; off >>= 1)
        lsum += __shfl_xor_sync(0xffffffffu, lsum, off);
    if ((tid & 31) == 0) red[tid >> 5] = lsum;
    __syncthreads();
    if (tid == 0) {
        float s = 0.f;
        #pragma unroll
        for (int i = 0; i < 8; i++) s += red[i];
        atomicAdd(&g_loss_sum, (double)s);
        __threadfence();
        unsigned old = atomicAdd(&g_done, 1u);
        if (old == NTILES - 1) {       // last CTA finalizes the loss
            __threadfence();
            double ls = g_loss_sum;
            out[LOSS_OFF] = (float)(1.25 * ls / (double)OUT_ELEMS);
        }
    }
}

// ---------------------------------------------------------------------------
extern "C" void kernel_launch(void* const* d_in, const int* in_sizes, int n_in,
                              void* d_out, int out_size) {
    const float* x = (const float*)d_in[0];   // [32,64,64,64] f32
    const float* w = (const float*)d_in[1];   // [1024,64] f32
    float* out = (float*)d_out;

    const int SMEM_BYTES = SMEM_FLOATS * 4;
    cudaFuncSetAttribute(vq_main, cudaFuncAttributeMaxDynamicSharedMemorySize,
                         SMEM_BYTES);

    vq_prep<<<16, 256>>>(w);
    vq_main<<<NTILES, 256, SMEM_BYTES>>>(x, w, out);
}